// round 1
// baseline (speedup 1.0000x reference)
#include <cuda_runtime.h>
#include <cuda_bf16.h>

#define NN 50000
#define EE 800000
#define RR 8
#define HH 128

// ---------------- scratch (device globals; no allocation allowed) ----------------
__device__ float    g_xw[(size_t)RR * NN * HH];   // per-relation transformed features
__device__ float    g_sq[RR * NN];
__device__ float    g_sk[RR * NN];
__device__ float    g_alpha[EE];
__device__ unsigned g_menc[NN];
__device__ float    g_h1[(size_t)NN * HH];
__device__ float    g_h2[(size_t)NN * HH];
__device__ int      g_counts[NN];
__device__ int      g_off[NN + 1];
__device__ int      g_cursor[NN];
__device__ int      g_sorted[EE];
__device__ float    g_wlt[HH * HH];

// ---------------- helpers ----------------
__device__ __forceinline__ unsigned fenc(float f) {
    unsigned u = __float_as_uint(f);
    return (u & 0x80000000u) ? ~u : (u | 0x80000000u);
}
__device__ __forceinline__ float fdec(unsigned u) {
    unsigned b = (u & 0x80000000u) ? (u ^ 0x80000000u) : ~u;
    return __uint_as_float(b);
}

// ---------------- GEMM: C[r][m][h] = sum_k A[m][k] * B[r][k][h] (+bias) ----------------
// Also (optionally) computes sq[r][m] = C_row . qv, sk[r][m] = C_row . kv in epilogue.
// TM=64, TN=128 (full H), 256 threads, thread tile 8x4.
__global__ void gemm128(const float* __restrict__ A, const float* __restrict__ Bmat,
                        float* __restrict__ C, int M,
                        const float* __restrict__ qv, const float* __restrict__ kv,
                        float* __restrict__ sq, float* __restrict__ sk,
                        const float* __restrict__ bias)
{
    const int r = blockIdx.y;
    const float* B = Bmat + (size_t)r * HH * HH;
    float* Cr = C + (size_t)r * M * HH;
    const int row0 = blockIdx.x * 64;
    const int tid = threadIdx.x;
    const int tx = tid & 31;
    const int ty = tid >> 5;

    __shared__ float As[64][16];
    __shared__ float Bs[16][128];

    float acc[8][4];
#pragma unroll
    for (int i = 0; i < 8; i++)
#pragma unroll
        for (int j = 0; j < 4; j++) acc[i][j] = 0.f;

    for (int k0 = 0; k0 < 128; k0 += 16) {
        // A tile 64x16 (256 float4 loads, 1 per thread)
        {
            int row = tid >> 2;
            int kk = (tid & 3) << 2;
            int gr = row0 + row;
            float4 v = make_float4(0.f, 0.f, 0.f, 0.f);
            if (gr < M) v = *reinterpret_cast<const float4*>(A + (size_t)gr * 128 + k0 + kk);
            *reinterpret_cast<float4*>(&As[row][kk]) = v;
        }
        // B tile 16x128 (512 float4, 2 per thread)
#pragma unroll
        for (int it = 0; it < 2; it++) {
            int idx = tid + it * 256;
            int row = idx >> 5;
            int c4 = (idx & 31) << 2;
            float4 v = *reinterpret_cast<const float4*>(B + (size_t)(k0 + row) * 128 + c4);
            *reinterpret_cast<float4*>(&Bs[row][c4]) = v;
        }
        __syncthreads();
#pragma unroll
        for (int k = 0; k < 16; k++) {
            float4 b4 = *reinterpret_cast<const float4*>(&Bs[k][tx << 2]);
#pragma unroll
            for (int i = 0; i < 8; i++) {
                float a = As[(ty << 3) + i][k];
                acc[i][0] += a * b4.x;
                acc[i][1] += a * b4.y;
                acc[i][2] += a * b4.z;
                acc[i][3] += a * b4.w;
            }
        }
        __syncthreads();
    }

    float q4[4], k4[4], bb[4];
    if (qv) {
#pragma unroll
        for (int j = 0; j < 4; j++) { q4[j] = qv[(tx << 2) + j]; k4[j] = kv[(tx << 2) + j]; }
    }
    if (bias) {
#pragma unroll
        for (int j = 0; j < 4; j++) bb[j] = bias[(tx << 2) + j];
    }

#pragma unroll
    for (int i = 0; i < 8; i++) {
        int gr = row0 + (ty << 3) + i;
        if (bias) {
#pragma unroll
            for (int j = 0; j < 4; j++) acc[i][j] += bb[j];
        }
        if (gr < M) {
            float4 v = make_float4(acc[i][0], acc[i][1], acc[i][2], acc[i][3]);
            *reinterpret_cast<float4*>(Cr + (size_t)gr * 128 + (tx << 2)) = v;
        }
        if (qv) {
            float pq = acc[i][0] * q4[0] + acc[i][1] * q4[1] + acc[i][2] * q4[2] + acc[i][3] * q4[3];
            float pk = acc[i][0] * k4[0] + acc[i][1] * k4[1] + acc[i][2] * k4[2] + acc[i][3] * k4[3];
#pragma unroll
            for (int off = 16; off > 0; off >>= 1) {
                pq += __shfl_down_sync(0xffffffffu, pq, off);
                pk += __shfl_down_sync(0xffffffffu, pk, off);
            }
            if (tx == 0 && gr < M) {
                sq[(size_t)r * M + gr] = pq;
                sk[(size_t)r * M + gr] = pk;
            }
        }
    }
}

// ---------------- CSR build (tgt is identical across both layers) ----------------
__global__ void zero_counts_kernel() {
    int n = blockIdx.x * blockDim.x + threadIdx.x;
    if (n < NN) g_counts[n] = 0;
}
__global__ void hist_kernel(const int* __restrict__ tgt) {
    int e = blockIdx.x * blockDim.x + threadIdx.x;
    if (e < EE) atomicAdd(&g_counts[tgt[e]], 1);
}
__global__ void scan_kernel() {
    __shared__ int part[1024];
    const int tid = threadIdx.x;
    const int CH = (NN + 1023) / 1024;
    const int st = tid * CH;
    int s = 0;
    for (int i = 0; i < CH; i++) {
        int idx = st + i;
        if (idx < NN) s += g_counts[idx];
    }
    part[tid] = s;
    __syncthreads();
    for (int off = 1; off < 1024; off <<= 1) {
        int add = (tid >= off) ? part[tid - off] : 0;
        __syncthreads();
        part[tid] += add;
        __syncthreads();
    }
    int run = (tid == 0) ? 0 : part[tid - 1];
    for (int i = 0; i < CH; i++) {
        int idx = st + i;
        if (idx < NN) {
            g_off[idx] = run;
            run += g_counts[idx];
        }
    }
    if (tid == 1023) g_off[NN] = part[1023];
}
__global__ void copy_cursor_kernel() {
    int n = blockIdx.x * blockDim.x + threadIdx.x;
    if (n < NN) g_cursor[n] = g_off[n];
}
__global__ void scatter_kernel(const int* __restrict__ tgt) {
    int e = blockIdx.x * blockDim.x + threadIdx.x;
    if (e < EE) {
        int pos = atomicAdd(&g_cursor[tgt[e]], 1);
        g_sorted[pos] = e;
    }
}

// ---------------- attention logits + segment max ----------------
__global__ void minit_kernel() {
    int n = blockIdx.x * blockDim.x + threadIdx.x;
    if (n < NN) g_menc[n] = 0u;
}
__global__ void alpha_kernel(const int* __restrict__ src, const int* __restrict__ tgt,
                             const int* __restrict__ et)
{
    int e = blockIdx.x * blockDim.x + threadIdx.x;
    if (e >= EE) return;
    int t = tgt[e], s = src[e], r = et[e];
    float a = g_sq[r * NN + t] + g_sk[r * NN + s];
    a = (a > 0.f) ? a : 0.2f * a;
    g_alpha[e] = a;
    atomicMax(&g_menc[t], fenc(a));
}

// ---------------- per-node softmax + weighted aggregation (no feature atomics) -------
__global__ void agg_kernel(const int* __restrict__ src, const int* __restrict__ et,
                           const float* __restrict__ bias, float* __restrict__ Y)
{
    const int n = blockIdx.x;
    const int h = threadIdx.x;  // 128
    const int beg = g_off[n], end = g_off[n + 1];
    const float m = fdec(g_menc[n]);
    float acc = 0.f, den = 0.f;
    for (int i = beg; i < end; i++) {
        int e = g_sorted[i];
        float w = __expf(g_alpha[e] - m);
        int s = src[e];
        int r = et[e];
        den += w;
        acc += w * g_xw[((size_t)r * NN + s) * HH + h];
    }
    float v = acc / (den + 1e-16f) + bias[h];
    v = fmaxf(v, 0.f);  // both RGAT layers are followed by ReLU
    Y[(size_t)n * HH + h] = v;
}

// ---------------- Wl transpose (final linear uses h @ Wl^T) ----------------
__global__ void transpose_kernel(const float* __restrict__ Wl) {
    int idx = blockIdx.x * blockDim.x + threadIdx.x;  // 16384
    if (idx < HH * HH) {
        int o = idx / HH, hc = idx % HH;
        g_wlt[hc * HH + o] = Wl[o * HH + hc];
    }
}

// ---------------- launch ----------------
extern "C" void kernel_launch(void* const* d_in, const int* in_sizes, int n_in,
                              void* d_out, int out_size)
{
    const float* x  = (const float*)d_in[0];
    const int*   ei = (const int*)d_in[1];
    const int*   et = (const int*)d_in[2];
    // d_in[3] = batch (unused: equal-size sorted graphs -> plain reshape)
    const float* W1 = (const float*)d_in[4];
    const float* q1 = (const float*)d_in[5];
    const float* k1 = (const float*)d_in[6];
    const float* b1 = (const float*)d_in[7];
    const float* W2 = (const float*)d_in[8];
    const float* q2 = (const float*)d_in[9];
    const float* k2 = (const float*)d_in[10];
    const float* b2 = (const float*)d_in[11];
    const float* Wl = (const float*)d_in[12];
    const float* bl = (const float*)d_in[13];
    const int* src = ei;
    const int* tgt = ei + EE;

    float *p_xw, *p_h1, *p_h2, *p_wlt, *p_sq, *p_sk;
    cudaGetSymbolAddress((void**)&p_xw, g_xw);
    cudaGetSymbolAddress((void**)&p_h1, g_h1);
    cudaGetSymbolAddress((void**)&p_h2, g_h2);
    cudaGetSymbolAddress((void**)&p_wlt, g_wlt);
    cudaGetSymbolAddress((void**)&p_sq, g_sq);
    cudaGetSymbolAddress((void**)&p_sk, g_sk);

    const int EB = (EE + 255) / 256;
    const int NB = (NN + 255) / 256;
    const int MB = (NN + 63) / 64;

    // CSR by target (shared by both layers)
    zero_counts_kernel<<<NB, 256>>>();
    hist_kernel<<<EB, 256>>>(tgt);
    scan_kernel<<<1, 1024>>>();
    copy_cursor_kernel<<<NB, 256>>>();
    scatter_kernel<<<EB, 256>>>(tgt);

    transpose_kernel<<<(HH * HH + 255) / 256, 256>>>(Wl);

    // ---- layer 1 ----
    gemm128<<<dim3(MB, RR), 256>>>(x, W1, p_xw, NN, q1, k1, p_sq, p_sk, nullptr);
    minit_kernel<<<NB, 256>>>();
    alpha_kernel<<<EB, 256>>>(src, tgt, et);
    agg_kernel<<<NN, HH>>>(src, et, b1, p_h1);

    // ---- layer 2 ----
    gemm128<<<dim3(MB, RR), 256>>>(p_h1, W2, p_xw, NN, q2, k2, p_sq, p_sk, nullptr);
    minit_kernel<<<NB, 256>>>();
    alpha_kernel<<<EB, 256>>>(src, tgt, et);
    agg_kernel<<<NN, HH>>>(src, et, b2, p_h2);

    // ---- final linear straight into d_out ([B,NPG,H] is contiguous [N,H]) ----
    gemm128<<<dim3(MB, 1), 256>>>(p_h2, p_wlt, (float*)d_out, NN,
                                  nullptr, nullptr, nullptr, nullptr, bl);
}